// round 3
// baseline (speedup 1.0000x reference)
#include <cuda_runtime.h>
#include <math.h>

#define NN 30000
#define TT 4
#define FIN 256
#define HH 64
#define HEADS 4
#define DD 256
#define EE 240000
#define ETOT 270000            // EE + NN self loops
#define NEG_SLOPE 0.2f

// ---------------- scratch (device globals: allocation-free) ----------------
__device__ __align__(16) float g_h0[TT * NN * HH];     // xWp output (t-major); reused as blend M (NN*DD)
__device__ __align__(16) float g_hp[TT * NN * DD];     // per-layer hp = h @ W
__device__ __align__(16) float g_bufA[TT * NN * DD];   // layer0 agg -> h1
__device__ __align__(16) float g_bufB[TT * NN * DD];   // layer1 agg -> embs
__device__ __align__(16) float g_es[TT * NN * HEADS];
__device__ __align__(16) float g_ed[TT * NN * HEADS];
__device__ __align__(16) float g_z[TT * NN * HEADS];
__device__ __align__(16) float g_w[TT * ETOT * HEADS];
__device__ __align__(16) float g_colsum[TT * DD];
__device__ float g_attn[TT];

// ---------------- utility ----------------
__global__ void zero_kernel(float4* __restrict__ p, int n4) {
    int i = blockIdx.x * blockDim.x + threadIdx.x;
    if (i < n4) p[i] = make_float4(0.f, 0.f, 0.f, 0.f);
}

__device__ __forceinline__ float eluf(float x) { return x > 0.f ? x : expm1f(x); }

// ---------------- fp32 SIMT GEMM: C(R x Nc) = A(R x K) @ B(K x Nc) (+bias) ----------------
// 64x64 block tile, BK=16, 256 threads, 4x4 per thread.
// permT!=0: output row remap (n,t)->(t*permN+n) where r = n*permT + t.
__global__ void __launch_bounds__(256) gemm_bias(
    const float* __restrict__ A, const float* __restrict__ B,
    const float* __restrict__ bias, float* __restrict__ C,
    int Rows, int K, int Ncols, int permT, int permN)
{
    __shared__ float As[16][64];
    __shared__ float Bs[16][64];
    const int tid = threadIdx.x;
    const int tm = tid >> 4;          // 0..15
    const int tn = tid & 15;          // 0..15
    const int rowBase = blockIdx.y << 6;
    const int colBase = blockIdx.x << 6;
    const int ar = tid >> 2;          // 0..63
    const int ac = (tid & 3) << 2;    // 0,4,8,12
    const int br = tid >> 4;          // 0..15
    const int bc = (tid & 15) << 2;   // 0..60

    float acc[4][4];
#pragma unroll
    for (int i = 0; i < 4; i++)
#pragma unroll
        for (int j = 0; j < 4; j++) acc[i][j] = 0.f;

    const bool aValid = (rowBase + ar) < Rows;
    const float* Ap = A + (size_t)(rowBase + ar) * K + ac;
    const float* Bp = B + (size_t)br * Ncols + colBase + bc;

    for (int kk = 0; kk < K; kk += 16) {
        float4 av = make_float4(0.f, 0.f, 0.f, 0.f);
        if (aValid) av = *(const float4*)(Ap + kk);
        float4 bv = *(const float4*)(Bp + (size_t)kk * Ncols);
        As[ac + 0][ar] = av.x;
        As[ac + 1][ar] = av.y;
        As[ac + 2][ar] = av.z;
        As[ac + 3][ar] = av.w;
        *(float4*)&Bs[br][bc] = bv;
        __syncthreads();
#pragma unroll
        for (int k = 0; k < 16; k++) {
            float4 a = *(const float4*)&As[k][tm << 2];
            float4 b = *(const float4*)&Bs[k][tn << 2];
            acc[0][0] += a.x * b.x; acc[0][1] += a.x * b.y; acc[0][2] += a.x * b.z; acc[0][3] += a.x * b.w;
            acc[1][0] += a.y * b.x; acc[1][1] += a.y * b.y; acc[1][2] += a.y * b.z; acc[1][3] += a.y * b.w;
            acc[2][0] += a.z * b.x; acc[2][1] += a.z * b.y; acc[2][2] += a.z * b.z; acc[2][3] += a.z * b.w;
            acc[3][0] += a.w * b.x; acc[3][1] += a.w * b.y; acc[3][2] += a.w * b.z; acc[3][3] += a.w * b.w;
        }
        __syncthreads();
    }

    float4 bb = make_float4(0.f, 0.f, 0.f, 0.f);
    if (bias) bb = *(const float4*)(bias + colBase + (tn << 2));
#pragma unroll
    for (int i = 0; i < 4; i++) {
        int r = rowBase + (tm << 2) + i;
        if (r >= Rows) break;
        int orow = permT ? ((r % permT) * permN + r / permT) : r;
        float4 o;
        o.x = acc[i][0] + bb.x; o.y = acc[i][1] + bb.y;
        o.z = acc[i][2] + bb.z; o.w = acc[i][3] + bb.w;
        *(float4*)(C + (size_t)orow * Ncols + colBase + (tn << 2)) = o;
    }
}

// ---------------- per-row attention logits: es/ed from hp ----------------
// one warp per (t,n) row; lane covers 8 consecutive cols (all in one head).
__global__ void __launch_bounds__(256) esed_kernel(
    const float* __restrict__ a_src, const float* __restrict__ a_dst)
{
    int gw = (blockIdx.x * 256 + threadIdx.x) >> 5;
    int lane = threadIdx.x & 31;
    if (gw >= TT * NN) return;
    const float* row = g_hp + (size_t)gw * DD;
    int base = lane * 8;
    float4 v0 = *(const float4*)(row + base);
    float4 v1 = *(const float4*)(row + base + 4);
    float4 s0 = *(const float4*)(a_src + base);
    float4 s1 = *(const float4*)(a_src + base + 4);
    float4 d0 = *(const float4*)(a_dst + base);
    float4 d1 = *(const float4*)(a_dst + base + 4);
    float s = v0.x * s0.x + v0.y * s0.y + v0.z * s0.z + v0.w * s0.w
            + v1.x * s1.x + v1.y * s1.y + v1.z * s1.z + v1.w * s1.w;
    float d = v0.x * d0.x + v0.y * d0.y + v0.z * d0.z + v0.w * d0.w
            + v1.x * d1.x + v1.y * d1.y + v1.z * d1.z + v1.w * d1.w;
#pragma unroll
    for (int off = 4; off > 0; off >>= 1) {
        s += __shfl_down_sync(0xffffffffu, s, off, 8);
        d += __shfl_down_sync(0xffffffffu, d, off, 8);
    }
    if ((lane & 7) == 0) {
        int h = lane >> 3;
        g_es[gw * HEADS + h] = s;
        g_ed[gw * HEADS + h] = d;
    }
}

// ---------------- edge pass A: w = exp(leaky(es[src]+ed[dst])), z[dst] += w ----------------
__global__ void __launch_bounds__(256) edge_pass_a(const int* __restrict__ ei)
{
    int idx = blockIdx.x * 256 + threadIdx.x;
    if (idx >= TT * ETOT) return;
    int t = idx / ETOT;
    int e = idx - t * ETOT;
    int s, d;
    if (e < EE) { s = ei[e]; d = ei[EE + e]; }
    else        { s = e - EE; d = s; }
    float4 es = *(const float4*)(g_es + ((size_t)t * NN + s) * HEADS);
    float4 ed = *(const float4*)(g_ed + ((size_t)t * NN + d) * HEADS);
    float4 w;
    float v;
    v = es.x + ed.x; v = v > 0.f ? v : NEG_SLOPE * v; w.x = expf(v);
    v = es.y + ed.y; v = v > 0.f ? v : NEG_SLOPE * v; w.y = expf(v);
    v = es.z + ed.z; v = v > 0.f ? v : NEG_SLOPE * v; w.z = expf(v);
    v = es.w + ed.w; v = v > 0.f ? v : NEG_SLOPE * v; w.w = expf(v);
    *(float4*)(g_w + (size_t)idx * HEADS) = w;
    float* zp = g_z + ((size_t)t * NN + d) * HEADS;
    atomicAdd(zp + 0, w.x);
    atomicAdd(zp + 1, w.y);
    atomicAdd(zp + 2, w.z);
    atomicAdd(zp + 3, w.w);
}

// ---------------- edge pass B: agg[dst] += alpha * hp[src] (warp per edge) ----------------
__global__ void __launch_bounds__(256) edge_pass_b(const int* __restrict__ ei,
                                                   float* __restrict__ agg)
{
    int gw = (blockIdx.x * 256 + threadIdx.x) >> 5;
    int lane = threadIdx.x & 31;
    if (gw >= TT * ETOT) return;
    int t = gw / ETOT;
    int e = gw - t * ETOT;
    int s, d;
    if (e < EE) { s = __ldg(ei + e); d = __ldg(ei + EE + e); }
    else        { s = e - EE; d = s; }
    float4 w = *(const float4*)(g_w + (size_t)gw * HEADS);
    float4 z = *(const float4*)(g_z + ((size_t)t * NN + d) * HEADS);
    float a0 = w.x / (z.x + 1e-16f);
    float a1 = w.y / (z.y + 1e-16f);
    float a2 = w.z / (z.z + 1e-16f);
    float a3 = w.w / (z.w + 1e-16f);
    const float* hpR = g_hp + ((size_t)t * NN + s) * DD;
    float* agR = agg + ((size_t)t * NN + d) * DD;
    int c0 = lane * 8;
    int h = c0 >> 6;
    float a = (h == 0) ? a0 : (h == 1) ? a1 : (h == 2) ? a2 : a3;
    float4 h0v = *(const float4*)(hpR + c0);
    float4 h1v = *(const float4*)(hpR + c0 + 4);
    atomicAdd(agR + c0 + 0, a * h0v.x);
    atomicAdd(agR + c0 + 1, a * h0v.y);
    atomicAdd(agR + c0 + 2, a * h0v.z);
    atomicAdd(agR + c0 + 3, a * h0v.w);
    atomicAdd(agR + c0 + 4, a * h1v.x);
    atomicAdd(agR + c0 + 5, a * h1v.y);
    atomicAdd(agR + c0 + 6, a * h1v.z);
    atomicAdd(agR + c0 + 7, a * h1v.w);
}

// ---------------- finalize: buf = ELU(buf + bias) (in place) ----------------
__global__ void __launch_bounds__(256) finalize_kernel(float* __restrict__ buf,
                                                       const float* __restrict__ bias)
{
    int i = blockIdx.x * 256 + threadIdx.x;
    if (i >= TT * NN * DD / 4) return;
    float4 v = ((float4*)buf)[i];
    int c = (i * 4) & (DD - 1);
    float4 b = *(const float4*)(bias + c);
    v.x = eluf(v.x + b.x);
    v.y = eluf(v.y + b.y);
    v.z = eluf(v.z + b.z);
    v.w = eluf(v.w + b.w);
    ((float4*)buf)[i] = v;
}

// ---------------- per-t column sums of embs (bufB) ----------------
__global__ void __launch_bounds__(256) colsum_kernel()
{
    int t = blockIdx.y;
    int c = threadIdx.x;
    float s = 0.f;
    for (int n = blockIdx.x; n < NN; n += gridDim.x)
        s += g_bufB[((size_t)t * NN + n) * DD + c];
    atomicAdd(&g_colsum[t * DD + c], s);
}

// ---------------- temporal attention weights (single block) ----------------
__global__ void __launch_bounds__(256) attn_kernel(
    const float* __restrict__ Wq, const float* __restrict__ bq,
    const float* __restrict__ Wk, const float* __restrict__ bk)
{
    __shared__ float mean[TT][DD];
    __shared__ float Kt[TT][DD];
    __shared__ float Qv[DD];
    __shared__ float red[256];
    __shared__ float sc[TT];
    int c = threadIdx.x;
#pragma unroll
    for (int t = 0; t < TT; t++)
        mean[t][c] = g_colsum[t * DD + c] * (1.0f / (float)NN);
    __syncthreads();
#pragma unroll
    for (int t = 0; t < TT; t++) {
        float acc = bk[c];
        for (int f = 0; f < DD; f++) acc += mean[t][f] * Wk[f * DD + c];
        Kt[t][c] = acc;
    }
    {
        float acc = bq[c];
        for (int f = 0; f < DD; f++) acc += mean[TT - 1][f] * Wq[f * DD + c];
        Qv[c] = acc;
    }
    __syncthreads();
    for (int t = 0; t < TT; t++) {
        red[c] = Qv[c] * Kt[t][c];
        __syncthreads();
        for (int off = 128; off > 0; off >>= 1) {
            if (c < off) red[c] += red[c + off];
            __syncthreads();
        }
        if (c == 0) sc[t] = red[0] * (1.0f / 16.0f);   // 1/sqrt(256)
        __syncthreads();
    }
    if (c == 0) {
        float m = fmaxf(fmaxf(sc[0], sc[1]), fmaxf(sc[2], sc[3]));
        float w0 = expf(sc[0] - m), w1 = expf(sc[1] - m);
        float w2 = expf(sc[2] - m), w3 = expf(sc[3] - m);
        float inv = 1.0f / (w0 + w1 + w2 + w3);
        g_attn[0] = w0 * inv; g_attn[1] = w1 * inv;
        g_attn[2] = w2 * inv; g_attn[3] = w3 * inv;
    }
}

// ---------------- blend: M = sum_t attn[t] * embs_t (into g_h0) ----------------
__global__ void __launch_bounds__(256) blend_kernel()
{
    int i = blockIdx.x * 256 + threadIdx.x;
    if (i >= NN * DD / 4) return;
    float a0 = g_attn[0], a1 = g_attn[1], a2 = g_attn[2], a3 = g_attn[3];
    const float4* b = (const float4*)g_bufB;
    const int stride = NN * DD / 4;
    float4 v0 = b[i];
    float4 v1 = b[i + stride];
    float4 v2 = b[i + 2 * stride];
    float4 v3 = b[i + 3 * stride];
    float4 m;
    m.x = a0 * v0.x + a1 * v1.x + a2 * v2.x + a3 * v3.x;
    m.y = a0 * v0.y + a1 * v1.y + a2 * v2.y + a3 * v3.y;
    m.z = a0 * v0.z + a1 * v1.z + a2 * v2.z + a3 * v3.z;
    m.w = a0 * v0.w + a1 * v1.w + a2 * v2.w + a3 * v3.w;
    ((float4*)g_h0)[i] = m;
}

// ---------------- launch ----------------
extern "C" void kernel_launch(void* const* d_in, const int* in_sizes, int n_in,
                              void* d_out, int out_size)
{
    const float* x      = (const float*)d_in[0];
    const int*   ei     = (const int*)  d_in[1];
    const float* Wp     = (const float*)d_in[2];
    const float* bp     = (const float*)d_in[3];
    const float* W0     = (const float*)d_in[4];
    const float* a_src0 = (const float*)d_in[5];
    const float* a_dst0 = (const float*)d_in[6];
    const float* b0     = (const float*)d_in[7];
    const float* W1     = (const float*)d_in[8];
    const float* a_src1 = (const float*)d_in[9];
    const float* a_dst1 = (const float*)d_in[10];
    const float* b1     = (const float*)d_in[11];
    const float* Wq     = (const float*)d_in[12];
    const float* bq     = (const float*)d_in[13];
    const float* Wk     = (const float*)d_in[14];
    const float* bk     = (const float*)d_in[15];
    const float* Wv     = (const float*)d_in[16];
    const float* bv     = (const float*)d_in[17];

    float *h0, *hp, *bufA, *bufB, *zz, *cs;
    cudaGetSymbolAddress((void**)&h0,   g_h0);
    cudaGetSymbolAddress((void**)&hp,   g_hp);
    cudaGetSymbolAddress((void**)&bufA, g_bufA);
    cudaGetSymbolAddress((void**)&bufB, g_bufB);
    cudaGetSymbolAddress((void**)&zz,   g_z);
    cudaGetSymbolAddress((void**)&cs,   g_colsum);

    const int rowsTN = TT * NN;            // 120000
    const int aggN4  = TT * NN * DD / 4;   // 7,680,000
    const int zN4    = TT * NN * HEADS / 4;
    const int edges  = TT * ETOT;          // 1,080,000

    // 1. h0(t,n) = x[n,t] @ Wp + bp   (rows ordered (n,t) -> permuted output)
    gemm_bias<<<dim3(HH / 64, rowsTN / 64), 256>>>(x, Wp, bp, h0, rowsTN, FIN, HH, TT, NN);

    // ---- GAT layer 0 ----
    zero_kernel<<<(aggN4 + 255) / 256, 256>>>((float4*)bufA, aggN4);
    zero_kernel<<<(zN4 + 255) / 256, 256>>>((float4*)zz, zN4);
    gemm_bias<<<dim3(DD / 64, rowsTN / 64), 256>>>(h0, W0, nullptr, hp, rowsTN, HH, DD, 0, 0);
    esed_kernel<<<rowsTN / 8, 256>>>(a_src0, a_dst0);
    edge_pass_a<<<(edges + 255) / 256, 256>>>(ei);
    edge_pass_b<<<edges / 8, 256>>>(ei, bufA);
    finalize_kernel<<<(aggN4 + 255) / 256, 256>>>(bufA, b0);

    // ---- GAT layer 1 ----
    zero_kernel<<<(aggN4 + 255) / 256, 256>>>((float4*)bufB, aggN4);
    zero_kernel<<<(zN4 + 255) / 256, 256>>>((float4*)zz, zN4);
    gemm_bias<<<dim3(DD / 64, rowsTN / 64), 256>>>(bufA, W1, nullptr, hp, rowsTN, DD, DD, 0, 0);
    esed_kernel<<<rowsTN / 8, 256>>>(a_src1, a_dst1);
    edge_pass_a<<<(edges + 255) / 256, 256>>>(ei);
    edge_pass_b<<<edges / 8, 256>>>(ei, bufB);
    finalize_kernel<<<(aggN4 + 255) / 256, 256>>>(bufB, b1);

    // ---- temporal attention ----
    zero_kernel<<<1, 256>>>((float4*)cs, TT * DD / 4);
    colsum_kernel<<<dim3(128, TT), 256>>>();
    attn_kernel<<<1, 256>>>(Wq, bq, Wk, bk);
    blend_kernel<<<(NN * DD / 4 + 255) / 256, 256>>>();

    // ---- out = M @ Wv + bv ----
    gemm_bias<<<dim3(DD / 64, (NN + 63) / 64), 256>>>(h0, Wv, bv, (float*)d_out, NN, DD, DD, 0, 0);
}

// round 4
// speedup vs baseline: 3.0926x; 3.0926x over previous
#include <cuda_runtime.h>
#include <math.h>

#define NN 30000
#define TT 4
#define FIN 256
#define HH 64
#define HEADS 4
#define DD 256
#define EE 240000
#define ETOT 270000            // EE + NN self loops
#define NEG_SLOPE 0.2f
#define NB_SCAN 118            // ceil(NN/256)

// ---------------- scratch (device globals: allocation-free) ----------------
__device__ __align__(16) float g_h0[TT * NN * HH];     // xWp output (t-major); reused as blend M (NN*DD)
__device__ __align__(16) float g_hp[TT * NN * DD];     // per-layer hp = h @ W
__device__ __align__(16) float g_bufA[TT * NN * DD];   // layer0 output (post ELU)
__device__ __align__(16) float g_bufB[TT * NN * DD];   // layer1 output (embs)
__device__ __align__(16) float g_es[TT * NN * HEADS];
__device__ __align__(16) float g_ed[TT * NN * HEADS];
__device__ __align__(16) float g_colsum[TT * DD];
__device__ float g_attn[TT];
// CSR
__device__ int g_deg[NN];
__device__ int g_off[NN];
__device__ int g_cursor[NN];
__device__ int g_part[256];
__device__ int g_srcs[ETOT];

// ---------------- utility ----------------
__global__ void zero_kernel(float4* __restrict__ p, int n4) {
    int i = blockIdx.x * blockDim.x + threadIdx.x;
    if (i < n4) p[i] = make_float4(0.f, 0.f, 0.f, 0.f);
}

__device__ __forceinline__ float eluf(float x) { return x > 0.f ? x : expm1f(x); }

// ---------------- CSR build ----------------
__global__ void hist_kernel(const int* __restrict__ ei) {
    int e = blockIdx.x * 256 + threadIdx.x;
    if (e >= ETOT) return;
    int d = (e < EE) ? ei[EE + e] : (e - EE);
    atomicAdd(&g_deg[d], 1);
}

__global__ void scan1_kernel() {
    __shared__ int sh[256];
    int tid = threadIdx.x;
    int i = blockIdx.x * 256 + tid;
    int v = (i < NN) ? g_deg[i] : 0;
    sh[tid] = v;
    __syncthreads();
#pragma unroll
    for (int off = 1; off < 256; off <<= 1) {
        int t = (tid >= off) ? sh[tid - off] : 0;
        __syncthreads();
        sh[tid] += t;
        __syncthreads();
    }
    if (i < NN) g_off[i] = sh[tid] - v;       // exclusive (local)
    if (tid == 255) g_part[blockIdx.x] = sh[255];
}

__global__ void scan2_kernel() {
    __shared__ int sh[256];
    int tid = threadIdx.x;
    int v = (tid < NB_SCAN) ? g_part[tid] : 0;
    sh[tid] = v;
    __syncthreads();
#pragma unroll
    for (int off = 1; off < 256; off <<= 1) {
        int t = (tid >= off) ? sh[tid - off] : 0;
        __syncthreads();
        sh[tid] += t;
        __syncthreads();
    }
    if (tid < NB_SCAN) g_part[tid] = sh[tid] - v;  // exclusive
}

__global__ void scan3_kernel() {
    int i = blockIdx.x * 256 + threadIdx.x;
    if (i < NN) {
        int o = g_off[i] + g_part[blockIdx.x];
        g_off[i] = o;
        g_cursor[i] = o;
    }
}

__global__ void scatter_kernel(const int* __restrict__ ei) {
    int e = blockIdx.x * 256 + threadIdx.x;
    if (e >= ETOT) return;
    int s, d;
    if (e < EE) { s = ei[e]; d = ei[EE + e]; }
    else        { s = e - EE; d = s; }
    int pos = atomicAdd(&g_cursor[d], 1);
    g_srcs[pos] = s;
}

// ---------------- fp32 SIMT GEMM 64x64 (used for xWp with output perm) ----------------
__global__ void __launch_bounds__(256) gemm_bias(
    const float* __restrict__ A, const float* __restrict__ B,
    const float* __restrict__ bias, float* __restrict__ C,
    int Rows, int K, int Ncols, int permT, int permN)
{
    __shared__ float As[16][64];
    __shared__ float Bs[16][64];
    const int tid = threadIdx.x;
    const int tm = tid >> 4;
    const int tn = tid & 15;
    const int rowBase = blockIdx.y << 6;
    const int colBase = blockIdx.x << 6;
    const int ar = tid >> 2;
    const int ac = (tid & 3) << 2;
    const int br = tid >> 4;
    const int bc = (tid & 15) << 2;

    float acc[4][4];
#pragma unroll
    for (int i = 0; i < 4; i++)
#pragma unroll
        for (int j = 0; j < 4; j++) acc[i][j] = 0.f;

    const bool aValid = (rowBase + ar) < Rows;
    const float* Ap = A + (size_t)(rowBase + ar) * K + ac;
    const float* Bp = B + (size_t)br * Ncols + colBase + bc;

    for (int kk = 0; kk < K; kk += 16) {
        float4 av = make_float4(0.f, 0.f, 0.f, 0.f);
        if (aValid) av = *(const float4*)(Ap + kk);
        float4 bv = *(const float4*)(Bp + (size_t)kk * Ncols);
        As[ac + 0][ar] = av.x;
        As[ac + 1][ar] = av.y;
        As[ac + 2][ar] = av.z;
        As[ac + 3][ar] = av.w;
        *(float4*)&Bs[br][bc] = bv;
        __syncthreads();
#pragma unroll
        for (int k = 0; k < 16; k++) {
            float4 a = *(const float4*)&As[k][tm << 2];
            float4 b = *(const float4*)&Bs[k][tn << 2];
            acc[0][0] += a.x * b.x; acc[0][1] += a.x * b.y; acc[0][2] += a.x * b.z; acc[0][3] += a.x * b.w;
            acc[1][0] += a.y * b.x; acc[1][1] += a.y * b.y; acc[1][2] += a.y * b.z; acc[1][3] += a.y * b.w;
            acc[2][0] += a.z * b.x; acc[2][1] += a.z * b.y; acc[2][2] += a.z * b.z; acc[2][3] += a.z * b.w;
            acc[3][0] += a.w * b.x; acc[3][1] += a.w * b.y; acc[3][2] += a.w * b.z; acc[3][3] += a.w * b.w;
        }
        __syncthreads();
    }

    float4 bb = make_float4(0.f, 0.f, 0.f, 0.f);
    if (bias) bb = *(const float4*)(bias + colBase + (tn << 2));
#pragma unroll
    for (int i = 0; i < 4; i++) {
        int r = rowBase + (tm << 2) + i;
        if (r >= Rows) break;
        int orow = permT ? ((r % permT) * permN + r / permT) : r;
        float4 o;
        o.x = acc[i][0] + bb.x; o.y = acc[i][1] + bb.y;
        o.z = acc[i][2] + bb.z; o.w = acc[i][3] + bb.w;
        *(float4*)(C + (size_t)orow * Ncols + colBase + (tn << 2)) = o;
    }
}

// ---------------- fp32 SIMT GEMM 128x128, 8x8 per thread ----------------
__global__ void __launch_bounds__(256) gemm128(
    const float* __restrict__ A, const float* __restrict__ B,
    const float* __restrict__ bias, float* __restrict__ C,
    int Rows, int K, int Ncols)
{
    __shared__ float As[16][128];
    __shared__ float Bs[16][128];
    const int tid = threadIdx.x;
    const int tx = tid & 15;          // col group (8 cols)
    const int ty = tid >> 4;          // row group (8 rows)
    const int rowBase = blockIdx.y << 7;
    const int colBase = blockIdx.x << 7;

    const int ar = tid >> 2;          // 0..63, handles rows ar & ar+64
    const int ac = (tid & 3) << 2;    // 0,4,8,12
    const int br = tid >> 5;          // 0..7, handles rows br & br+8
    const int bc = (tid & 31) << 2;   // 0..124

    float acc[8][8];
#pragma unroll
    for (int i = 0; i < 8; i++)
#pragma unroll
        for (int j = 0; j < 8; j++) acc[i][j] = 0.f;

    const int r0 = rowBase + ar;
    const int r1 = r0 + 64;
    const bool v0 = r0 < Rows;
    const bool v1 = r1 < Rows;
    const float* A0 = A + (size_t)r0 * K + ac;
    const float* A1 = A + (size_t)r1 * K + ac;
    const float* Bp = B + (size_t)br * Ncols + colBase + bc;

    for (int kk = 0; kk < K; kk += 16) {
        float4 a0 = make_float4(0.f, 0.f, 0.f, 0.f);
        float4 a1 = make_float4(0.f, 0.f, 0.f, 0.f);
        if (v0) a0 = *(const float4*)(A0 + kk);
        if (v1) a1 = *(const float4*)(A1 + kk);
        float4 bv0 = *(const float4*)(Bp + (size_t)kk * Ncols);
        float4 bv1 = *(const float4*)(Bp + (size_t)(kk + 8) * Ncols);
        As[ac + 0][ar] = a0.x; As[ac + 1][ar] = a0.y;
        As[ac + 2][ar] = a0.z; As[ac + 3][ar] = a0.w;
        As[ac + 0][ar + 64] = a1.x; As[ac + 1][ar + 64] = a1.y;
        As[ac + 2][ar + 64] = a1.z; As[ac + 3][ar + 64] = a1.w;
        *(float4*)&Bs[br][bc] = bv0;
        *(float4*)&Bs[br + 8][bc] = bv1;
        __syncthreads();
#pragma unroll
        for (int k = 0; k < 16; k++) {
            float ra[8], rb[8];
            float4 t0 = *(const float4*)&As[k][ty << 3];
            float4 t1 = *(const float4*)&As[k][(ty << 3) + 4];
            ra[0] = t0.x; ra[1] = t0.y; ra[2] = t0.z; ra[3] = t0.w;
            ra[4] = t1.x; ra[5] = t1.y; ra[6] = t1.z; ra[7] = t1.w;
            float4 u0 = *(const float4*)&Bs[k][tx << 3];
            float4 u1 = *(const float4*)&Bs[k][(tx << 3) + 4];
            rb[0] = u0.x; rb[1] = u0.y; rb[2] = u0.z; rb[3] = u0.w;
            rb[4] = u1.x; rb[5] = u1.y; rb[6] = u1.z; rb[7] = u1.w;
#pragma unroll
            for (int i = 0; i < 8; i++)
#pragma unroll
                for (int j = 0; j < 8; j++)
                    acc[i][j] += ra[i] * rb[j];
        }
        __syncthreads();
    }

    float4 bb0 = make_float4(0.f, 0.f, 0.f, 0.f);
    float4 bb1 = make_float4(0.f, 0.f, 0.f, 0.f);
    if (bias) {
        bb0 = *(const float4*)(bias + colBase + (tx << 3));
        bb1 = *(const float4*)(bias + colBase + (tx << 3) + 4);
    }
#pragma unroll
    for (int i = 0; i < 8; i++) {
        int r = rowBase + (ty << 3) + i;
        if (r < Rows) {
            float4 o0, o1;
            o0.x = acc[i][0] + bb0.x; o0.y = acc[i][1] + bb0.y;
            o0.z = acc[i][2] + bb0.z; o0.w = acc[i][3] + bb0.w;
            o1.x = acc[i][4] + bb1.x; o1.y = acc[i][5] + bb1.y;
            o1.z = acc[i][6] + bb1.z; o1.w = acc[i][7] + bb1.w;
            float* cp = C + (size_t)r * Ncols + colBase + (tx << 3);
            *(float4*)cp = o0;
            *(float4*)(cp + 4) = o1;
        }
    }
}

// ---------------- per-row attention logits: es/ed from hp ----------------
__global__ void __launch_bounds__(256) esed_kernel(
    const float* __restrict__ a_src, const float* __restrict__ a_dst)
{
    int gw = (blockIdx.x * 256 + threadIdx.x) >> 5;
    int lane = threadIdx.x & 31;
    if (gw >= TT * NN) return;
    const float* row = g_hp + (size_t)gw * DD;
    int base = lane * 8;
    float4 v0 = *(const float4*)(row + base);
    float4 v1 = *(const float4*)(row + base + 4);
    float4 s0 = *(const float4*)(a_src + base);
    float4 s1 = *(const float4*)(a_src + base + 4);
    float4 d0 = *(const float4*)(a_dst + base);
    float4 d1 = *(const float4*)(a_dst + base + 4);
    float s = v0.x * s0.x + v0.y * s0.y + v0.z * s0.z + v0.w * s0.w
            + v1.x * s1.x + v1.y * s1.y + v1.z * s1.z + v1.w * s1.w;
    float d = v0.x * d0.x + v0.y * d0.y + v0.z * d0.z + v0.w * d0.w
            + v1.x * d1.x + v1.y * d1.y + v1.z * d1.z + v1.w * d1.w;
#pragma unroll
    for (int off = 4; off > 0; off >>= 1) {
        s += __shfl_down_sync(0xffffffffu, s, off, 8);
        d += __shfl_down_sync(0xffffffffu, d, off, 8);
    }
    if ((lane & 7) == 0) {
        int h = lane >> 3;
        g_es[gw * HEADS + h] = s;
        g_ed[gw * HEADS + h] = d;
    }
}

// ---------------- fused softmax + aggregation: warp per (t, dst) ----------------
// out[t,d,:] = ELU( sum_{e in in(d)} alpha_e * hp[t, src_e, :] + bias )
__global__ void __launch_bounds__(256) agg_kernel(const float* __restrict__ bias,
                                                  float* __restrict__ out)
{
    int gw = (blockIdx.x * 256 + threadIdx.x) >> 5;
    int lane = threadIdx.x & 31;
    if (gw >= TT * NN) return;
    int t = gw / NN;
    int d = gw - t * NN;
    int base = g_off[d];
    int deg = g_deg[d];
    const size_t tN = (size_t)t * NN;
    const float* edp = g_ed + (size_t)gw * HEADS;

    // ---- pass 1: z per head (8 edges x 4 heads per iteration) ----
    float ed_q = __ldg(edp + (lane & 3));
    float z = 0.f;
    for (int j0 = 0; j0 < deg; j0 += 8) {
        int j = j0 + (lane >> 2);
        if (j < deg) {
            int s = g_srcs[base + j];
            float es = __ldg(g_es + (tN + s) * HEADS + (lane & 3));
            float v = es + ed_q;
            v = v > 0.f ? v : NEG_SLOPE * v;
            z += expf(v);
        }
    }
    z += __shfl_xor_sync(0xffffffffu, z, 4);
    z += __shfl_xor_sync(0xffffffffu, z, 8);
    z += __shfl_xor_sync(0xffffffffu, z, 16);
    int myh = lane >> 3;                          // head of my 8 output cols
    float zh = __shfl_sync(0xffffffffu, z, myh);  // lane myh holds head myh
    float zinv = 1.f / (zh + 1e-16f);
    float edh = __ldg(edp + myh);

    // ---- pass 2: weighted accumulation ----
    float4 a0 = make_float4(0.f, 0.f, 0.f, 0.f);
    float4 a1 = make_float4(0.f, 0.f, 0.f, 0.f);
    for (int j = 0; j < deg; j++) {
        int s = g_srcs[base + j];
        float es = __ldg(g_es + (tN + s) * HEADS + myh);
        float v = es + edh;
        v = v > 0.f ? v : NEG_SLOPE * v;
        float alpha = expf(v) * zinv;
        const float4* r = (const float4*)(g_hp + (tN + s) * DD) + lane * 2;
        float4 u0 = __ldg(r);
        float4 u1 = __ldg(r + 1);
        a0.x += alpha * u0.x; a0.y += alpha * u0.y;
        a0.z += alpha * u0.z; a0.w += alpha * u0.w;
        a1.x += alpha * u1.x; a1.y += alpha * u1.y;
        a1.z += alpha * u1.z; a1.w += alpha * u1.w;
    }

    // ---- epilogue: bias + ELU, single write ----
    const float4* bp4 = (const float4*)bias + lane * 2;
    float4 b0v = __ldg(bp4), b1v = __ldg(bp4 + 1);
    float4 o0, o1;
    o0.x = eluf(a0.x + b0v.x); o0.y = eluf(a0.y + b0v.y);
    o0.z = eluf(a0.z + b0v.z); o0.w = eluf(a0.w + b0v.w);
    o1.x = eluf(a1.x + b1v.x); o1.y = eluf(a1.y + b1v.y);
    o1.z = eluf(a1.z + b1v.z); o1.w = eluf(a1.w + b1v.w);
    float4* op = (float4*)(out + (size_t)gw * DD) + lane * 2;
    op[0] = o0;
    op[1] = o1;
}

// ---------------- per-t column sums of embs (bufB) ----------------
__global__ void __launch_bounds__(256) colsum_kernel()
{
    int t = blockIdx.y;
    int c = threadIdx.x;
    float s = 0.f;
    for (int n = blockIdx.x; n < NN; n += gridDim.x)
        s += g_bufB[((size_t)t * NN + n) * DD + c];
    atomicAdd(&g_colsum[t * DD + c], s);
}

// ---------------- temporal attention weights (single block) ----------------
__global__ void __launch_bounds__(256) attn_kernel(
    const float* __restrict__ Wq, const float* __restrict__ bq,
    const float* __restrict__ Wk, const float* __restrict__ bk)
{
    __shared__ float mean[TT][DD];
    __shared__ float Kt[TT][DD];
    __shared__ float Qv[DD];
    __shared__ float red[256];
    __shared__ float sc[TT];
    int c = threadIdx.x;
#pragma unroll
    for (int t = 0; t < TT; t++)
        mean[t][c] = g_colsum[t * DD + c] * (1.0f / (float)NN);
    __syncthreads();
#pragma unroll
    for (int t = 0; t < TT; t++) {
        float acc = bk[c];
        for (int f = 0; f < DD; f++) acc += mean[t][f] * Wk[f * DD + c];
        Kt[t][c] = acc;
    }
    {
        float acc = bq[c];
        for (int f = 0; f < DD; f++) acc += mean[TT - 1][f] * Wq[f * DD + c];
        Qv[c] = acc;
    }
    __syncthreads();
    for (int t = 0; t < TT; t++) {
        red[c] = Qv[c] * Kt[t][c];
        __syncthreads();
        for (int off = 128; off > 0; off >>= 1) {
            if (c < off) red[c] += red[c + off];
            __syncthreads();
        }
        if (c == 0) sc[t] = red[0] * (1.0f / 16.0f);   // 1/sqrt(256)
        __syncthreads();
    }
    if (c == 0) {
        float m = fmaxf(fmaxf(sc[0], sc[1]), fmaxf(sc[2], sc[3]));
        float w0 = expf(sc[0] - m), w1 = expf(sc[1] - m);
        float w2 = expf(sc[2] - m), w3 = expf(sc[3] - m);
        float inv = 1.0f / (w0 + w1 + w2 + w3);
        g_attn[0] = w0 * inv; g_attn[1] = w1 * inv;
        g_attn[2] = w2 * inv; g_attn[3] = w3 * inv;
    }
}

// ---------------- blend: M = sum_t attn[t] * embs_t (into g_h0) ----------------
__global__ void __launch_bounds__(256) blend_kernel()
{
    int i = blockIdx.x * 256 + threadIdx.x;
    if (i >= NN * DD / 4) return;
    float a0 = g_attn[0], a1 = g_attn[1], a2 = g_attn[2], a3 = g_attn[3];
    const float4* b = (const float4*)g_bufB;
    const int stride = NN * DD / 4;
    float4 v0 = b[i];
    float4 v1 = b[i + stride];
    float4 v2 = b[i + 2 * stride];
    float4 v3 = b[i + 3 * stride];
    float4 m;
    m.x = a0 * v0.x + a1 * v1.x + a2 * v2.x + a3 * v3.x;
    m.y = a0 * v0.y + a1 * v1.y + a2 * v2.y + a3 * v3.y;
    m.z = a0 * v0.z + a1 * v1.z + a2 * v2.z + a3 * v3.z;
    m.w = a0 * v0.w + a1 * v1.w + a2 * v2.w + a3 * v3.w;
    ((float4*)g_h0)[i] = m;
}

// ---------------- launch ----------------
extern "C" void kernel_launch(void* const* d_in, const int* in_sizes, int n_in,
                              void* d_out, int out_size)
{
    const float* x      = (const float*)d_in[0];
    const int*   ei     = (const int*)  d_in[1];
    const float* Wp     = (const float*)d_in[2];
    const float* bp     = (const float*)d_in[3];
    const float* W0     = (const float*)d_in[4];
    const float* a_src0 = (const float*)d_in[5];
    const float* a_dst0 = (const float*)d_in[6];
    const float* b0     = (const float*)d_in[7];
    const float* W1     = (const float*)d_in[8];
    const float* a_src1 = (const float*)d_in[9];
    const float* a_dst1 = (const float*)d_in[10];
    const float* b1     = (const float*)d_in[11];
    const float* Wq     = (const float*)d_in[12];
    const float* bq     = (const float*)d_in[13];
    const float* Wk     = (const float*)d_in[14];
    const float* bk     = (const float*)d_in[15];
    const float* Wv     = (const float*)d_in[16];
    const float* bv     = (const float*)d_in[17];

    float *h0, *hp, *bufA, *bufB, *cs;
    int *degp;
    cudaGetSymbolAddress((void**)&h0,   g_h0);
    cudaGetSymbolAddress((void**)&hp,   g_hp);
    cudaGetSymbolAddress((void**)&bufA, g_bufA);
    cudaGetSymbolAddress((void**)&bufB, g_bufB);
    cudaGetSymbolAddress((void**)&cs,   g_colsum);
    cudaGetSymbolAddress((void**)&degp, g_deg);

    const int rowsTN = TT * NN;            // 120000
    const int edges  = ETOT;               // 270000
    const int warpsTN = TT * NN;           // agg warps

    // ---- CSR build (graph shared across t and both layers) ----
    zero_kernel<<<(NN / 4 + 255) / 256, 256>>>((float4*)degp, NN / 4);
    hist_kernel<<<(edges + 255) / 256, 256>>>(ei);
    scan1_kernel<<<NB_SCAN, 256>>>();
    scan2_kernel<<<1, 256>>>();
    scan3_kernel<<<NB_SCAN, 256>>>();
    scatter_kernel<<<(edges + 255) / 256, 256>>>(ei);

    // 1. h0(t,n) = x[n,t] @ Wp + bp   (rows ordered (n,t) -> permuted output)
    gemm_bias<<<dim3(1, rowsTN / 64), 256>>>(x, Wp, bp, h0, rowsTN, FIN, HH, TT, NN);

    // ---- GAT layer 0 ----
    gemm128<<<dim3(DD / 128, (rowsTN + 127) / 128), 256>>>(h0, W0, nullptr, hp, rowsTN, HH, DD);
    esed_kernel<<<rowsTN / 8, 256>>>(a_src0, a_dst0);
    agg_kernel<<<(warpsTN + 7) / 8, 256>>>(b0, bufA);

    // ---- GAT layer 1 ----
    gemm128<<<dim3(DD / 128, (rowsTN + 127) / 128), 256>>>(bufA, W1, nullptr, hp, rowsTN, DD, DD);
    esed_kernel<<<rowsTN / 8, 256>>>(a_src1, a_dst1);
    agg_kernel<<<(warpsTN + 7) / 8, 256>>>(b1, bufB);

    // ---- temporal attention ----
    zero_kernel<<<1, 256>>>((float4*)cs, TT * DD / 4);
    colsum_kernel<<<dim3(128, TT), 256>>>();
    attn_kernel<<<1, 256>>>(Wq, bq, Wk, bk);
    blend_kernel<<<(NN * DD / 4 + 255) / 256, 256>>>();

    // ---- out = M @ Wv + bv ----
    gemm128<<<dim3(DD / 128, (NN + 127) / 128), 256>>>(h0, Wv, bv, (float*)d_out, NN, DD, DD);
}

// round 5
// speedup vs baseline: 4.0871x; 1.3216x over previous
#include <cuda_runtime.h>
#include <math.h>
#include <stdint.h>

#define NN 30000
#define TT 4
#define FIN 256
#define HH 64
#define HEADS 4
#define DD 256
#define EE 240000
#define ETOT 270000            // EE + NN self loops
#define NEG_SLOPE 0.2f
#define NB_SCAN 118            // ceil(NN/256)

// ---------------- scratch (device globals: allocation-free) ----------------
__device__ __align__(16) float g_h0[TT * NN * HH];     // xWp output (t-major); reused as blend M (NN*DD)
__device__ __align__(16) float g_hp[TT * NN * DD];     // per-layer hp = h @ W
__device__ __align__(16) float g_bufA[TT * NN * DD];   // layer0 output (post ELU)
__device__ __align__(16) float g_bufB[TT * NN * DD];   // layer1 output (embs)
__device__ __align__(16) float g_es[TT * NN * HEADS];
__device__ __align__(16) float g_ed[TT * NN * HEADS];
__device__ __align__(16) float g_colsum[TT * DD];
__device__ float g_attn[TT];
// CSR
__device__ int g_deg[NN];
__device__ int g_off[NN];
__device__ int g_cursor[NN];
__device__ int g_part[256];
__device__ int g_srcs[ETOT];

// ---------------- utility ----------------
__global__ void zero_kernel(float4* __restrict__ p, int n4) {
    int i = blockIdx.x * blockDim.x + threadIdx.x;
    if (i < n4) p[i] = make_float4(0.f, 0.f, 0.f, 0.f);
}

__device__ __forceinline__ float eluf(float x) { return x > 0.f ? x : expm1f(x); }

__device__ __forceinline__ uint32_t f2tf32(float x) {
    uint32_t r;
    asm("cvt.rna.tf32.f32 %0, %1;" : "=r"(r) : "f"(x));
    return r;
}

__device__ __forceinline__ void mma_tf32(float* c, const uint32_t* a, const uint32_t* b) {
    asm volatile(
        "mma.sync.aligned.m16n8k8.row.col.f32.tf32.tf32.f32 "
        "{%0,%1,%2,%3}, {%4,%5,%6,%7}, {%8,%9}, {%0,%1,%2,%3};"
        : "+f"(c[0]), "+f"(c[1]), "+f"(c[2]), "+f"(c[3])
        : "r"(a[0]), "r"(a[1]), "r"(a[2]), "r"(a[3]), "r"(b[0]), "r"(b[1]));
}

// ---------------- CSR build ----------------
__global__ void hist_kernel(const int* __restrict__ ei) {
    int e = blockIdx.x * 256 + threadIdx.x;
    if (e >= ETOT) return;
    int d = (e < EE) ? ei[EE + e] : (e - EE);
    atomicAdd(&g_deg[d], 1);
}

__global__ void scan1_kernel() {
    __shared__ int sh[256];
    int tid = threadIdx.x;
    int i = blockIdx.x * 256 + tid;
    int v = (i < NN) ? g_deg[i] : 0;
    sh[tid] = v;
    __syncthreads();
#pragma unroll
    for (int off = 1; off < 256; off <<= 1) {
        int t = (tid >= off) ? sh[tid - off] : 0;
        __syncthreads();
        sh[tid] += t;
        __syncthreads();
    }
    if (i < NN) g_off[i] = sh[tid] - v;       // exclusive (local)
    if (tid == 255) g_part[blockIdx.x] = sh[255];
}

__global__ void scan2_kernel() {
    __shared__ int sh[256];
    int tid = threadIdx.x;
    int v = (tid < NB_SCAN) ? g_part[tid] : 0;
    sh[tid] = v;
    __syncthreads();
#pragma unroll
    for (int off = 1; off < 256; off <<= 1) {
        int t = (tid >= off) ? sh[tid - off] : 0;
        __syncthreads();
        sh[tid] += t;
        __syncthreads();
    }
    if (tid < NB_SCAN) g_part[tid] = sh[tid] - v;  // exclusive
}

__global__ void scan3_kernel() {
    int i = blockIdx.x * 256 + threadIdx.x;
    if (i < NN) {
        int o = g_off[i] + g_part[blockIdx.x];
        g_off[i] = o;
        g_cursor[i] = o;
    }
}

__global__ void scatter_kernel(const int* __restrict__ ei) {
    int e = blockIdx.x * 256 + threadIdx.x;
    if (e >= ETOT) return;
    int s, d;
    if (e < EE) { s = ei[e]; d = ei[EE + e]; }
    else        { s = e - EE; d = s; }
    int pos = atomicAdd(&g_cursor[d], 1);
    g_srcs[pos] = s;
}

// ---------------- tf32 tensor-core GEMM: C(R x Nc) = A(R x K) @ B(K x Nc) (+bias) ----------------
// 128x128x32 tile, 256 threads, 8 warps (2x4), warp tile 64x32 via m16n8k8.
// Guarded B loads / C stores support Ncols < 128 (e.g. 64). K must be multiple of 32.
// permT!=0: output row remap r=(n*permT+t) -> t*permN+n.
__global__ void __launch_bounds__(256) gemm_tf32(
    const float* __restrict__ A, const float* __restrict__ B,
    const float* __restrict__ bias, float* __restrict__ C,
    int Rows, int K, int Ncols, int permT, int permN)
{
    __shared__ float As[32][136];   // [k][row], pad 8 -> frag banks = 8k+row (conflict-free)
    __shared__ float Bs[32][136];   // [k][col]
    const int tid = threadIdx.x;
    const int wid = tid >> 5;
    const int lane = tid & 31;
    const int wm = wid >> 2;        // 0..1
    const int wn = wid & 3;         // 0..3
    const int g = lane >> 2;        // 0..7
    const int t4 = lane & 3;        // 0..3
    const int rowBase = blockIdx.y << 7;
    const int colBase = blockIdx.x << 7;

    // global load mapping
    const int arow = tid >> 1;            // 0..127
    const int ak = (tid & 1) << 4;        // 0 / 16
    const int bcol = (lane) << 2;         // 0..124
    const int bk = wid;                   // 0..7 (rows bk, bk+8, bk+16, bk+24)

    float acc[4][4][4];
#pragma unroll
    for (int mi = 0; mi < 4; mi++)
#pragma unroll
        for (int ni = 0; ni < 4; ni++)
#pragma unroll
            for (int q = 0; q < 4; q++) acc[mi][ni][q] = 0.f;

    const int gr = rowBase + arow;
    const bool aOK = gr < Rows;
    const float* Ap = A + (size_t)(aOK ? gr : 0) * K + ak;
    const bool bOK = (colBase + bcol) < Ncols;
    const float* Bp = B + (size_t)bk * Ncols + colBase + bcol;

    for (int kk = 0; kk < K; kk += 32) {
        // load A 128x32 -> As[k][row] (tf32-converted, transposed)
#pragma unroll
        for (int i = 0; i < 4; i++) {
            float4 v = make_float4(0.f, 0.f, 0.f, 0.f);
            if (aOK) v = *(const float4*)(Ap + kk + i * 4);
            int kb = ak + i * 4;
            As[kb + 0][arow] = __uint_as_float(f2tf32(v.x));
            As[kb + 1][arow] = __uint_as_float(f2tf32(v.y));
            As[kb + 2][arow] = __uint_as_float(f2tf32(v.z));
            As[kb + 3][arow] = __uint_as_float(f2tf32(v.w));
        }
        // load B 32x128 -> Bs[k][col]
#pragma unroll
        for (int i = 0; i < 4; i++) {
            float4 v = make_float4(0.f, 0.f, 0.f, 0.f);
            if (bOK) v = *(const float4*)(Bp + (size_t)(kk + i * 8) * Ncols);
            float4 w;
            w.x = __uint_as_float(f2tf32(v.x));
            w.y = __uint_as_float(f2tf32(v.y));
            w.z = __uint_as_float(f2tf32(v.z));
            w.w = __uint_as_float(f2tf32(v.w));
            *(float4*)&Bs[bk + i * 8][bcol] = w;
        }
        __syncthreads();

#pragma unroll
        for (int ks = 0; ks < 4; ks++) {
            const int k0 = ks * 8;
            uint32_t afr[4][4];
            uint32_t bfr[4][2];
#pragma unroll
            for (int mi = 0; mi < 4; mi++) {
                int row = (wm << 6) + (mi << 4) + g;
                afr[mi][0] = __float_as_uint(As[k0 + t4][row]);
                afr[mi][1] = __float_as_uint(As[k0 + t4][row + 8]);
                afr[mi][2] = __float_as_uint(As[k0 + t4 + 4][row]);
                afr[mi][3] = __float_as_uint(As[k0 + t4 + 4][row + 8]);
            }
#pragma unroll
            for (int ni = 0; ni < 4; ni++) {
                int col = (wn << 5) + (ni << 3) + g;
                bfr[ni][0] = __float_as_uint(Bs[k0 + t4][col]);
                bfr[ni][1] = __float_as_uint(Bs[k0 + t4 + 4][col]);
            }
#pragma unroll
            for (int mi = 0; mi < 4; mi++)
#pragma unroll
                for (int ni = 0; ni < 4; ni++)
                    mma_tf32(acc[mi][ni], afr[mi], bfr[ni]);
        }
        __syncthreads();
    }

    // epilogue
#pragma unroll
    for (int mi = 0; mi < 4; mi++) {
        int row0 = rowBase + (wm << 6) + (mi << 4) + g;
        int row1 = row0 + 8;
        int orow0 = -1, orow1 = -1;
        if (row0 < Rows) orow0 = permT ? ((row0 % permT) * permN + row0 / permT) : row0;
        if (row1 < Rows) orow1 = permT ? ((row1 % permT) * permN + row1 / permT) : row1;
#pragma unroll
        for (int ni = 0; ni < 4; ni++) {
            int col = colBase + (wn << 5) + (ni << 3) + (t4 << 1);
            if (col < Ncols) {
                float bx = 0.f, by = 0.f;
                if (bias) { bx = bias[col]; by = bias[col + 1]; }
                if (orow0 >= 0) {
                    float* cp = C + (size_t)orow0 * Ncols + col;
                    cp[0] = acc[mi][ni][0] + bx;
                    cp[1] = acc[mi][ni][1] + by;
                }
                if (orow1 >= 0) {
                    float* cp = C + (size_t)orow1 * Ncols + col;
                    cp[0] = acc[mi][ni][2] + bx;
                    cp[1] = acc[mi][ni][3] + by;
                }
            }
        }
    }
}

// ---------------- per-row attention logits: es/ed from hp ----------------
__global__ void __launch_bounds__(256) esed_kernel(
    const float* __restrict__ a_src, const float* __restrict__ a_dst)
{
    int gw = (blockIdx.x * 256 + threadIdx.x) >> 5;
    int lane = threadIdx.x & 31;
    if (gw >= TT * NN) return;
    const float* row = g_hp + (size_t)gw * DD;
    int base = lane * 8;
    float4 v0 = *(const float4*)(row + base);
    float4 v1 = *(const float4*)(row + base + 4);
    float4 s0 = *(const float4*)(a_src + base);
    float4 s1 = *(const float4*)(a_src + base + 4);
    float4 d0 = *(const float4*)(a_dst + base);
    float4 d1 = *(const float4*)(a_dst + base + 4);
    float s = v0.x * s0.x + v0.y * s0.y + v0.z * s0.z + v0.w * s0.w
            + v1.x * s1.x + v1.y * s1.y + v1.z * s1.z + v1.w * s1.w;
    float d = v0.x * d0.x + v0.y * d0.y + v0.z * d0.z + v0.w * d0.w
            + v1.x * d1.x + v1.y * d1.y + v1.z * d1.z + v1.w * d1.w;
#pragma unroll
    for (int off = 4; off > 0; off >>= 1) {
        s += __shfl_down_sync(0xffffffffu, s, off, 8);
        d += __shfl_down_sync(0xffffffffu, d, off, 8);
    }
    if ((lane & 7) == 0) {
        int h = lane >> 3;
        g_es[gw * HEADS + h] = s;
        g_ed[gw * HEADS + h] = d;
    }
}

// ---------------- fused softmax + aggregation: warp per (t, dst) ----------------
__global__ void __launch_bounds__(256) agg_kernel(const float* __restrict__ bias,
                                                  float* __restrict__ out)
{
    int gw = (blockIdx.x * 256 + threadIdx.x) >> 5;
    int lane = threadIdx.x & 31;
    if (gw >= TT * NN) return;
    int t = gw / NN;
    int d = gw - t * NN;
    int base = g_off[d];
    int deg = g_deg[d];
    const size_t tN = (size_t)t * NN;
    const float* edp = g_ed + (size_t)gw * HEADS;

    // ---- pass 1: z per head (8 edges x 4 heads per iteration) ----
    float ed_q = __ldg(edp + (lane & 3));
    float z = 0.f;
    for (int j0 = 0; j0 < deg; j0 += 8) {
        int j = j0 + (lane >> 2);
        if (j < deg) {
            int s = g_srcs[base + j];
            float es = __ldg(g_es + (tN + s) * HEADS + (lane & 3));
            float v = es + ed_q;
            v = v > 0.f ? v : NEG_SLOPE * v;
            z += expf(v);
        }
    }
    z += __shfl_xor_sync(0xffffffffu, z, 4);
    z += __shfl_xor_sync(0xffffffffu, z, 8);
    z += __shfl_xor_sync(0xffffffffu, z, 16);
    int myh = lane >> 3;
    float zh = __shfl_sync(0xffffffffu, z, myh);
    float zinv = 1.f / (zh + 1e-16f);
    float edh = __ldg(edp + myh);

    // ---- pass 2: weighted accumulation ----
    float4 a0 = make_float4(0.f, 0.f, 0.f, 0.f);
    float4 a1 = make_float4(0.f, 0.f, 0.f, 0.f);
    for (int j = 0; j < deg; j++) {
        int s = g_srcs[base + j];
        float es = __ldg(g_es + (tN + s) * HEADS + myh);
        float v = es + edh;
        v = v > 0.f ? v : NEG_SLOPE * v;
        float alpha = expf(v) * zinv;
        const float4* r = (const float4*)(g_hp + (tN + s) * DD) + lane * 2;
        float4 u0 = __ldg(r);
        float4 u1 = __ldg(r + 1);
        a0.x += alpha * u0.x; a0.y += alpha * u0.y;
        a0.z += alpha * u0.z; a0.w += alpha * u0.w;
        a1.x += alpha * u1.x; a1.y += alpha * u1.y;
        a1.z += alpha * u1.z; a1.w += alpha * u1.w;
    }

    // ---- epilogue: bias + ELU, single write ----
    const float4* bp4 = (const float4*)bias + lane * 2;
    float4 b0v = __ldg(bp4), b1v = __ldg(bp4 + 1);
    float4 o0, o1;
    o0.x = eluf(a0.x + b0v.x); o0.y = eluf(a0.y + b0v.y);
    o0.z = eluf(a0.z + b0v.z); o0.w = eluf(a0.w + b0v.w);
    o1.x = eluf(a1.x + b1v.x); o1.y = eluf(a1.y + b1v.y);
    o1.z = eluf(a1.z + b1v.z); o1.w = eluf(a1.w + b1v.w);
    float4* op = (float4*)(out + (size_t)gw * DD) + lane * 2;
    op[0] = o0;
    op[1] = o1;
}

// ---------------- per-t column sums of embs (bufB) ----------------
__global__ void __launch_bounds__(256) colsum_kernel()
{
    int t = blockIdx.y;
    int c = threadIdx.x;
    float s = 0.f;
    for (int n = blockIdx.x; n < NN; n += gridDim.x)
        s += g_bufB[((size_t)t * NN + n) * DD + c];
    atomicAdd(&g_colsum[t * DD + c], s);
}

// ---------------- temporal attention weights (single block) ----------------
__global__ void __launch_bounds__(256) attn_kernel(
    const float* __restrict__ Wq, const float* __restrict__ bq,
    const float* __restrict__ Wk, const float* __restrict__ bk)
{
    __shared__ float mean[TT][DD];
    __shared__ float Kt[TT][DD];
    __shared__ float Qv[DD];
    __shared__ float red[256];
    __shared__ float sc[TT];
    int c = threadIdx.x;
#pragma unroll
    for (int t = 0; t < TT; t++)
        mean[t][c] = g_colsum[t * DD + c] * (1.0f / (float)NN);
    __syncthreads();
#pragma unroll
    for (int t = 0; t < TT; t++) {
        float acc = bk[c];
        for (int f = 0; f < DD; f++) acc += mean[t][f] * Wk[f * DD + c];
        Kt[t][c] = acc;
    }
    {
        float acc = bq[c];
        for (int f = 0; f < DD; f++) acc += mean[TT - 1][f] * Wq[f * DD + c];
        Qv[c] = acc;
    }
    __syncthreads();
    for (int t = 0; t < TT; t++) {
        red[c] = Qv[c] * Kt[t][c];
        __syncthreads();
        for (int off = 128; off > 0; off >>= 1) {
            if (c < off) red[c] += red[c + off];
            __syncthreads();
        }
        if (c == 0) sc[t] = red[0] * (1.0f / 16.0f);   // 1/sqrt(256)
        __syncthreads();
    }
    if (c == 0) {
        float m = fmaxf(fmaxf(sc[0], sc[1]), fmaxf(sc[2], sc[3]));
        float w0 = expf(sc[0] - m), w1 = expf(sc[1] - m);
        float w2 = expf(sc[2] - m), w3 = expf(sc[3] - m);
        float inv = 1.0f / (w0 + w1 + w2 + w3);
        g_attn[0] = w0 * inv; g_attn[1] = w1 * inv;
        g_attn[2] = w2 * inv; g_attn[3] = w3 * inv;
    }
}

// ---------------- blend: M = sum_t attn[t] * embs_t (into g_h0) ----------------
__global__ void __launch_bounds__(256) blend_kernel()
{
    int i = blockIdx.x * 256 + threadIdx.x;
    if (i >= NN * DD / 4) return;
    float a0 = g_attn[0], a1 = g_attn[1], a2 = g_attn[2], a3 = g_attn[3];
    const float4* b = (const float4*)g_bufB;
    const int stride = NN * DD / 4;
    float4 v0 = b[i];
    float4 v1 = b[i + stride];
    float4 v2 = b[i + 2 * stride];
    float4 v3 = b[i + 3 * stride];
    float4 m;
    m.x = a0 * v0.x + a1 * v1.x + a2 * v2.x + a3 * v3.x;
    m.y = a0 * v0.y + a1 * v1.y + a2 * v2.y + a3 * v3.y;
    m.z = a0 * v0.z + a1 * v1.z + a2 * v2.z + a3 * v3.z;
    m.w = a0 * v0.w + a1 * v1.w + a2 * v2.w + a3 * v3.w;
    ((float4*)g_h0)[i] = m;
}

// ---------------- launch ----------------
extern "C" void kernel_launch(void* const* d_in, const int* in_sizes, int n_in,
                              void* d_out, int out_size)
{
    const float* x      = (const float*)d_in[0];
    const int*   ei     = (const int*)  d_in[1];
    const float* Wp     = (const float*)d_in[2];
    const float* bp     = (const float*)d_in[3];
    const float* W0     = (const float*)d_in[4];
    const float* a_src0 = (const float*)d_in[5];
    const float* a_dst0 = (const float*)d_in[6];
    const float* b0     = (const float*)d_in[7];
    const float* W1     = (const float*)d_in[8];
    const float* a_src1 = (const float*)d_in[9];
    const float* a_dst1 = (const float*)d_in[10];
    const float* b1     = (const float*)d_in[11];
    const float* Wq     = (const float*)d_in[12];
    const float* bq     = (const float*)d_in[13];
    const float* Wk     = (const float*)d_in[14];
    const float* bk     = (const float*)d_in[15];
    const float* Wv     = (const float*)d_in[16];
    const float* bv     = (const float*)d_in[17];

    float *h0, *hp, *bufA, *bufB, *cs;
    int *degp;
    cudaGetSymbolAddress((void**)&h0,   g_h0);
    cudaGetSymbolAddress((void**)&hp,   g_hp);
    cudaGetSymbolAddress((void**)&bufA, g_bufA);
    cudaGetSymbolAddress((void**)&bufB, g_bufB);
    cudaGetSymbolAddress((void**)&cs,   g_colsum);
    cudaGetSymbolAddress((void**)&degp, g_deg);

    const int rowsTN = TT * NN;            // 120000
    const int edges  = ETOT;               // 270000
    const int gy = (rowsTN + 127) / 128;   // 938

    // ---- CSR build (graph shared across t and both layers) ----
    zero_kernel<<<(NN / 4 + 255) / 256, 256>>>((float4*)degp, NN / 4);
    hist_kernel<<<(edges + 255) / 256, 256>>>(ei);
    scan1_kernel<<<NB_SCAN, 256>>>();
    scan2_kernel<<<1, 256>>>();
    scan3_kernel<<<NB_SCAN, 256>>>();
    scatter_kernel<<<(edges + 255) / 256, 256>>>(ei);

    // 1. h0(t,n) = x[n,t] @ Wp + bp   (rows (n,t) -> permuted (t,n) output)
    gemm_tf32<<<dim3(1, gy), 256>>>(x, Wp, bp, h0, rowsTN, FIN, HH, TT, NN);

    // ---- GAT layer 0 ----
    gemm_tf32<<<dim3(2, gy), 256>>>(h0, W0, nullptr, hp, rowsTN, HH, DD, 0, 0);
    esed_kernel<<<rowsTN / 8, 256>>>(a_src0, a_dst0);
    agg_kernel<<<(rowsTN + 7) / 8, 256>>>(b0, bufA);

    // ---- GAT layer 1 ----
    gemm_tf32<<<dim3(2, gy), 256>>>(bufA, W1, nullptr, hp, rowsTN, DD, DD, 0, 0);
    esed_kernel<<<rowsTN / 8, 256>>>(a_src1, a_dst1);
    agg_kernel<<<(rowsTN + 7) / 8, 256>>>(b1, bufB);

    // ---- temporal attention ----
    zero_kernel<<<1, 256>>>((float4*)cs, TT * DD / 4);
    colsum_kernel<<<dim3(128, TT), 256>>>();
    attn_kernel<<<1, 256>>>(Wq, bq, Wk, bk);
    blend_kernel<<<(NN * DD / 4 + 255) / 256, 256>>>();

    // ---- out = M @ Wv + bv ----
    gemm_tf32<<<dim3(2, (NN + 127) / 128), 256>>>(h0, Wv, bv, (float*)d_out, NN, DD, DD, 0, 0);
}